// round 13
// baseline (speedup 1.0000x reference)
#include <cuda_runtime.h>
#include <cuda_fp16.h>
#include <math.h>
#include <stdint.h>

#define Bsz 8
#define Cc 1024
#define Ll 1024
#define Hh 16
#define Dk 64
#define NBH (Bsz*Hh)
#define SCALE 0.125f
#define NTB 8                       // number of t-blocks (128 each)

// ---------------------------------------------------------------------------
// Scratch (__device__ globals; no allocations allowed)
// ---------------------------------------------------------------------------
__device__ __half g_Whi[3][Cc*Cc];
__device__ __half g_xThi[3][(size_t)Bsz*Ll*Cc];   // [which][b][l][c]
__device__ __half g_qhi[(size_t)NBH*Ll*Dk];       // [bh][t][dk]
__device__ __half g_qlo[(size_t)NBH*Ll*Dk];
__device__ __half g_khi[(size_t)NBH*Ll*Dk];       // [bh][s][dk] (hi only)
__device__ __half g_vhi[(size_t)NBH*Dk*Ll];       // [bh][dk][s]
__device__ __half g_vlo[(size_t)NBH*Dk*Ll];       // used only pre-vscale
__device__ __half g_e [(size_t)NBH*Ll*Ll];        // 256 MB: E=exp(S) [bh][t][s]
__device__ float  g_pz[(size_t)NBH*NTB*Ll];       // partial colsum [bh][tb][s]
__device__ float  g_rz[NBH*Ll];                   // 1/z

#define SW128(o) ((uint32_t)(o) ^ ((((uint32_t)(o)) >> 3) & 0x70))

__device__ __forceinline__ uint32_t smem_u32(const void* p) {
    uint32_t a;
    asm("{ .reg .u64 t; cvta.to.shared.u64 t, %1; cvt.u32.u64 %0, t; }" : "=r"(a) : "l"(p));
    return a;
}
__device__ __forceinline__ void ldsm4(uint32_t* r, uint32_t addr) {
    asm volatile("ldmatrix.sync.aligned.m8n8.x4.shared.b16 {%0,%1,%2,%3}, [%4];"
                 : "=r"(r[0]), "=r"(r[1]), "=r"(r[2]), "=r"(r[3]) : "r"(addr));
}
__device__ __forceinline__ void mma16816(float* d, const uint32_t* a, const uint32_t* b) {
    asm volatile(
        "mma.sync.aligned.m16n8k16.row.col.f32.f16.f16.f32 "
        "{%0,%1,%2,%3}, {%4,%5,%6,%7}, {%8,%9}, {%0,%1,%2,%3};"
        : "+f"(d[0]), "+f"(d[1]), "+f"(d[2]), "+f"(d[3])
        : "r"(a[0]), "r"(a[1]), "r"(a[2]), "r"(a[3]), "r"(b[0]), "r"(b[1]));
}
__device__ __forceinline__ void cp16(uint32_t dst, const void* src) {
    asm volatile("cp.async.ca.shared.global [%0], [%1], 16;" :: "r"(dst), "l"(src));
}
#define CP_COMMIT() asm volatile("cp.async.commit_group;" ::: "memory")
#define CP_WAIT(n)  asm volatile("cp.async.wait_group %0;" :: "n"(n) : "memory")

// Async-load ROWS x 64 halfs (128B rows) into SW128-swizzled smem. 256 threads.
template <int ROWS>
__device__ __forceinline__ void load_tile_async(uint32_t dst, const __half* src,
                                                int stride_h, int tid) {
    #pragma unroll
    for (int i = 0; i < ROWS * 8 / 256; i++) {
        int idx = i * 256 + tid;
        int r = idx >> 3, cb = (idx & 7) * 16;
        cp16(dst + SW128(r * 128 + cb), (const char*)(src + (size_t)r * stride_h) + cb);
    }
}

// K=64 chunk of split-fp16 GEMM.
// NPROD=1: Ahi*Bhi.  NPROD=2: + Alo*Bhi.  NPROD=3: + Ahi*Blo.
template <int MF, int NF, int NPROD>
__device__ __forceinline__ void gemm_chunk(uint32_t saHi, uint32_t saLo,
                                           uint32_t sbHi, uint32_t sbLo,
                                           int m0, int n0, int lane,
                                           float acc[MF][NF][4]) {
    const int arow = lane & 15,                    acol8 = (lane >> 4) * 8;
    const int brow = (lane >> 4) * 8 + (lane & 7), bcol8 = ((lane >> 3) & 1) * 8;
    #pragma unroll
    for (int ks = 0; ks < 4; ks++) {
        const int k0 = ks * 16;
        uint32_t ahi[MF][4], alo[MF][4];
        #pragma unroll
        for (int mf = 0; mf < MF; mf++) {
            uint32_t off = SW128((m0 + mf * 16 + arow) * 128 + (k0 + acol8) * 2);
            ldsm4(ahi[mf], saHi + off);
            if (NPROD > 1) ldsm4(alo[mf], saLo + off);
        }
        uint32_t bhi[NF][2], blo[NF][2];
        #pragma unroll
        for (int p = 0; p < NF / 2; p++) {
            uint32_t off = SW128((n0 + p * 16 + brow) * 128 + (k0 + bcol8) * 2);
            uint32_t r[4];
            ldsm4(r, sbHi + off);
            bhi[p*2][0] = r[0]; bhi[p*2][1] = r[1];
            bhi[p*2+1][0] = r[2]; bhi[p*2+1][1] = r[3];
            if (NPROD > 2) {
                ldsm4(r, sbLo + off);
                blo[p*2][0] = r[0]; blo[p*2][1] = r[1];
                blo[p*2+1][0] = r[2]; blo[p*2+1][1] = r[3];
            }
        }
        #pragma unroll
        for (int mf = 0; mf < MF; mf++)
            #pragma unroll
            for (int nf = 0; nf < NF; nf++) {
                mma16816(acc[mf][nf], ahi[mf], bhi[nf]);
                if (NPROD > 1) mma16816(acc[mf][nf], alo[mf], bhi[nf]);
                if (NPROD > 2) mma16816(acc[mf][nf], ahi[mf], blo[nf]);
            }
    }
}

// ---------------------------------------------------------------------------
// Conversions (hi-only weights)
// ---------------------------------------------------------------------------
__global__ __launch_bounds__(256) void conv_w_all(const float* __restrict__ W0,
                                                  const float* __restrict__ W1,
                                                  const float* __restrict__ W2) {
    const int which = blockIdx.x >> 10;
    const float* W = (which == 0) ? W0 : (which == 1 ? W1 : W2);
    int i = ((blockIdx.x & 1023) * 256 + threadIdx.x) * 4;
    float4 v = *(const float4*)(W + i);
    __half2* H = (__half2*)(g_Whi[which] + i);
    H[0] = __halves2half2(__float2half_rn(v.x), __float2half_rn(v.y));
    H[1] = __halves2half2(__float2half_rn(v.z), __float2half_rn(v.w));
}

__global__ __launch_bounds__(256) void conv_xt_all(const float* __restrict__ x0,
                                                   const float* __restrict__ x1,
                                                   const float* __restrict__ x2) {
    __shared__ float tile[32][33];
    const int which = blockIdx.z >> 3, b = blockIdx.z & 7;
    const float* x = (which == 0) ? x0 : (which == 1 ? x1 : x2);
    const int c0 = blockIdx.y * 32, l0 = blockIdx.x * 32;
    const int tx = threadIdx.x, ty = threadIdx.y;
    const float* xb = x + (size_t)b * Cc * Ll;
    #pragma unroll
    for (int i = 0; i < 4; i++)
        tile[ty + i * 8][tx] = xb[(size_t)(c0 + ty + i * 8) * Ll + l0 + tx];
    __syncthreads();
    #pragma unroll
    for (int i = 0; i < 4; i++) {
        float vv = tile[tx][ty + i * 8];
        size_t o = (size_t)b * Ll * Cc + (size_t)(l0 + ty + i * 8) * Cc + c0 + tx;
        g_xThi[which][o] = __float2half_rn(vv);
    }
}

// ---------------------------------------------------------------------------
// Projection (all 3 in one launch): Y[o,l] = sum_c W[o,c] xT[l,c] + bias[o].
// Plain fp16 GEMM. 2-stage double-buffer (stage=32KB).
// q: hi+lo out; k: hi only; v: hi+lo out.
// ---------------------------------------------------------------------------
__global__ __launch_bounds__(256) void proj_mma(const float* __restrict__ bias0,
                                                const float* __restrict__ bias1,
                                                const float* __restrict__ bias2) {
    extern __shared__ char smem[];
    uint32_t sb = smem_u32(smem);
    const int tid = threadIdx.x, w = tid >> 5, lane = tid & 31;
    const int wm = w >> 1, wn = w & 1;
    const int which = blockIdx.z >> 3, b = blockIdx.z & 7;
    const int o0 = blockIdx.y * 128, l0 = blockIdx.x * 128;
    const float* bias = (which == 0) ? bias0 : (which == 1 ? bias1 : bias2);

    const __half* Whi = g_Whi[which] + (size_t)o0 * Cc;
    const __half* Xhi = g_xThi[which] + (size_t)b * Ll * Cc + (size_t)l0 * Cc;

    auto AH = [&](int st) { return sb + st * 32768; };
    auto BH = [&](int st) { return sb + st * 32768 + 16384; };

    load_tile_async<128>(AH(0), Whi, Cc, tid);
    load_tile_async<128>(BH(0), Xhi, Cc, tid);
    CP_COMMIT();

    float acc[2][8][4] = {};
    for (int it = 0; it < 16; it++) {
        if (it < 15) {
            const int c1 = (it + 1) * 64, st = (it + 1) & 1;
            load_tile_async<128>(AH(st), Whi + c1, Cc, tid);
            load_tile_async<128>(BH(st), Xhi + c1, Cc, tid);
            CP_COMMIT();
            CP_WAIT(1);
        } else {
            CP_WAIT(0);
        }
        __syncthreads();
        const int st = it & 1;
        gemm_chunk<2, 8, 1>(AH(st), AH(st), BH(st), BH(st),
                            wm * 32, wn * 64, lane, acc);
        __syncthreads();
    }

    const int gid = lane >> 2, tid4 = lane & 3;
    if (which < 2) {
        __half* Ls = (__half*)smem;                 // 128 x 128 halfs
        __half* Hp = (which == 0 ? g_qhi : g_khi);
        const int hh0 = o0 >> 6;
        const int npass = (which == 0) ? 2 : 1;     // k is hi-only
        for (int pass = 0; pass < npass; pass++) {
            #pragma unroll
            for (int mf = 0; mf < 2; mf++)
                #pragma unroll
                for (int h2 = 0; h2 < 2; h2++) {
                    const int o = wm * 32 + mf * 16 + gid + h2 * 8;
                    const float bi = bias[o0 + o];
                    #pragma unroll
                    for (int nf = 0; nf < 8; nf++)
                        #pragma unroll
                        for (int j = 0; j < 2; j++) {
                            const int l = wn * 64 + nf * 8 + tid4 * 2 + j;
                            float v = acc[mf][nf][h2 * 2 + j] + bi;
                            __half hi = __float2half_rn(v);
                            Ls[l * 128 + o] = pass == 0 ? hi
                                : __float2half_rn(v - __half2float(hi));
                        }
                }
            __syncthreads();
            __half* P = pass == 0 ? Hp : g_qlo;
            #pragma unroll
            for (int it = 0; it < 8; it++) {
                int cid = it * 256 + tid;
                int l_loc = cid >> 4, hh_loc = (cid >> 3) & 1, c16 = cid & 7;
                uint4 vv = *(uint4*)(Ls + l_loc * 128 + hh_loc * 64 + c16 * 8);
                size_t off = ((size_t)(b * Hh + hh0 + hh_loc) * Ll + l0 + l_loc) * Dk + c16 * 8;
                *(uint4*)(P + off) = vv;
            }
            __syncthreads();
        }
    } else {
        #pragma unroll
        for (int mf = 0; mf < 2; mf++)
            #pragma unroll
            for (int h2 = 0; h2 < 2; h2++) {
                const int o = o0 + wm * 32 + mf * 16 + gid + h2 * 8;
                const float bi = bias[o];
                const int hh = o >> 6, dk = o & 63;
                #pragma unroll
                for (int nf = 0; nf < 8; nf++) {
                    const int l = l0 + wn * 64 + nf * 8 + tid4 * 2;
                    float v0 = acc[mf][nf][h2 * 2 + 0] + bi;
                    float v1 = acc[mf][nf][h2 * 2 + 1] + bi;
                    __half hi0 = __float2half_rn(v0);
                    __half lo0 = __float2half_rn(v0 - __half2float(hi0));
                    __half hi1 = __float2half_rn(v1);
                    __half lo1 = __float2half_rn(v1 - __half2float(hi1));
                    size_t off = ((size_t)(b * Hh + hh) * Dk + dk) * Ll + l;
                    *(__half2*)(g_vhi + off) = __halves2half2(hi0, hi1);
                    *(__half2*)(g_vlo + off) = __halves2half2(lo0, lo1);
                }
            }
    }
}

// ---------------------------------------------------------------------------
// Scores: block = (s-quarter 256, t-block 128, bh); 2 s-subtiles per block,
// K double-buffered, Q resident. E written direct from registers.
// 2-product: Qhi*Khi + Qlo*Khi.
// smem: [QH 16K][QL 16K][K st0 16K][K st1 16K][smZ 2K] = 66KB
// ---------------------------------------------------------------------------
__global__ __launch_bounds__(256) void scores_mma() {
    extern __shared__ char smem[];
    uint32_t sb = smem_u32(smem);
    const int tid = threadIdx.x, w = tid >> 5, lane = tid & 31;
    const int wm = w >> 1, wn = w & 1;
    const int bh = blockIdx.z, t0 = blockIdx.y * 128, s0 = blockIdx.x * 256;

    auto KH = [&](int st) { return sb + 32768 + st * 16384; };
    float* smZ = (float*)(smem + 65536);

    const __half* Khb = g_khi + ((size_t)bh * Ll + s0) * Dk;

    load_tile_async<128>(sb,         g_qhi + ((size_t)bh * Ll + t0) * Dk, Dk, tid);
    load_tile_async<128>(sb + 16384, g_qlo + ((size_t)bh * Ll + t0) * Dk, Dk, tid);
    load_tile_async<128>(KH(0), Khb, Dk, tid);
    CP_COMMIT();

    __half* Eb = g_e + (size_t)bh * Ll * Ll;
    const int gid = lane >> 2, tid4 = lane & 3;

    #pragma unroll
    for (int sub = 0; sub < 2; sub++) {
        if (sub == 0) {
            load_tile_async<128>(KH(1), Khb + 128 * Dk, Dk, tid);
            CP_COMMIT();
            CP_WAIT(1);
        } else {
            CP_WAIT(0);
        }
        __syncthreads();

        float acc[2][8][4] = {};
        gemm_chunk<2, 8, 2>(sb, sb + 16384, KH(sub), KH(sub),
                            wm * 32, wn * 64, lane, acc);

        // exp in place (bounded logits: no max subtraction needed)
        #pragma unroll
        for (int mf = 0; mf < 2; mf++)
            #pragma unroll
            for (int nf = 0; nf < 8; nf++)
                #pragma unroll
                for (int e = 0; e < 4; e++)
                    acc[mf][nf][e] = __expf(acc[mf][nf][e] * SCALE);

        // Column partial sums over this block's 128 t: add-only reduction.
        #pragma unroll
        for (int nf = 0; nf < 8; nf++)
            #pragma unroll
            for (int j = 0; j < 2; j++) {
                float z = acc[0][nf][j] + acc[0][nf][2 + j]
                        + acc[1][nf][j] + acc[1][nf][2 + j];
                #pragma unroll
                for (int off = 4; off <= 16; off <<= 1)
                    z += __shfl_xor_sync(0xffffffffu, z, off);
                if (gid == 0)
                    smZ[(wn * 64 + nf * 8 + tid4 * 2 + j) * 4 + wm] = z;
            }
        __syncthreads();
        if (tid < 128) {
            float z = smZ[tid * 4] + smZ[tid * 4 + 1] + smZ[tid * 4 + 2] + smZ[tid * 4 + 3];
            g_pz[((size_t)bh * NTB + blockIdx.y) * Ll + s0 + sub * 128 + tid] = z;
        }

        // Write E (fp16) direct.
        #pragma unroll
        for (int mf = 0; mf < 2; mf++)
            #pragma unroll
            for (int h2 = 0; h2 < 2; h2++) {
                const int t = t0 + wm * 32 + mf * 16 + gid + h2 * 8;
                __half* rowp = Eb + (size_t)t * Ll;
                #pragma unroll
                for (int nf = 0; nf < 8; nf++) {
                    const int s = s0 + sub * 128 + wn * 64 + nf * 8 + tid4 * 2;
                    *(__half2*)(rowp + s) =
                        __halves2half2(__float2half_rn(acc[mf][nf][h2 * 2]),
                                       __float2half_rn(acc[mf][nf][h2 * 2 + 1]));
                }
            }
        __syncthreads();   // smZ reads done before next sub's writes
    }
}

// ---------------------------------------------------------------------------
// Merge partials -> rz = 1/z.  (adds only)
// ---------------------------------------------------------------------------
__global__ __launch_bounds__(256) void merge_stats() {
    const int bh = blockIdx.y;
    const int s = blockIdx.x * 256 + threadIdx.x;
    float z = 0.f;
    #pragma unroll
    for (int tb = 0; tb < NTB; tb++)
        z += g_pz[((size_t)bh * NTB + tb) * Ll + s];
    g_rz[bh * Ll + s] = 1.f / z;
}

// ---------------------------------------------------------------------------
// V pre-scale: V'hi = fp16((vhi+vlo) * rz[s]); lo no longer used downstream.
// ---------------------------------------------------------------------------
__global__ __launch_bounds__(256) void vscale_kernel() {
    int gid = blockIdx.x * 256 + threadIdx.x;      // half2 index
    int sp = (gid & 511) * 2;
    int bh = gid >> 15;                            // /(64 dk * 512 half2)
    __half2 h = ((__half2*)g_vhi)[gid];
    __half2 l = ((__half2*)g_vlo)[gid];
    float r0 = g_rz[bh * Ll + sp], r1 = g_rz[bh * Ll + sp + 1];
    float v0 = (__low2float(h)  + __low2float(l))  * r0;
    float v1 = (__high2float(h) + __high2float(l)) * r1;
    ((__half2*)g_vhi)[gid] =
        __halves2half2(__float2half_rn(v0), __float2half_rn(v1));
}

// ---------------------------------------------------------------------------
// Output: out[c,t] = sum_s E[t,s] V'[c,s].  Single-product double-buffered
// GEMM. Block 64(c) x 128(t); 8 warps (2m x 4n); 16 s-chunks of 64.
// stage = [E 16KB][Vhi 8KB] x2 = 48KB
// ---------------------------------------------------------------------------
__global__ __launch_bounds__(256) void out_mma(float* __restrict__ out) {
    extern __shared__ char smem[];
    uint32_t sb = smem_u32(smem);
    const int tid = threadIdx.x, w = tid >> 5, lane = tid & 31;
    const int wm = w >> 2, wn = w & 3;
    const int bh = blockIdx.y, t0 = blockIdx.x * 128;

    const __half* Ep = g_e + (size_t)bh * Ll * Ll + (size_t)t0 * Ll;
    const __half* Vh = g_vhi + (size_t)bh * Dk * Ll;

    auto EH = [&](int st) { return sb + st * 24576; };
    auto VH = [&](int st) { return sb + st * 24576 + 16384; };

    load_tile_async<128>(EH(0), Ep, Ll, tid);
    load_tile_async<64>(VH(0), Vh, Ll, tid);
    CP_COMMIT();

    float acc[2][4][4] = {};
    for (int it = 0; it < 16; it++) {
        if (it < 15) {
            const int s1 = (it + 1) * 64, st = (it + 1) & 1;
            load_tile_async<128>(EH(st), Ep + s1, Ll, tid);
            load_tile_async<64>(VH(st), Vh + s1, Ll, tid);
            CP_COMMIT();
            CP_WAIT(1);
        } else {
            CP_WAIT(0);
        }
        __syncthreads();
        const int st = it & 1;
        gemm_chunk<2, 4, 1>(VH(st), VH(st), EH(st), EH(st),
                            wm * 32, wn * 32, lane, acc);
        __syncthreads();
    }

    float* ob = out + (size_t)bh * Dk * Ll;
    const int gid = lane >> 2, tid4 = lane & 3;
    #pragma unroll
    for (int mf = 0; mf < 2; mf++)
        #pragma unroll
        for (int h2 = 0; h2 < 2; h2++) {
            const int c = wm * 32 + mf * 16 + gid + h2 * 8;
            #pragma unroll
            for (int nf = 0; nf < 4; nf++) {
                const int t = t0 + wn * 32 + nf * 8 + tid4 * 2;
                *(float2*)(ob + (size_t)c * Ll + t) =
                    make_float2(acc[mf][nf][h2 * 2], acc[mf][nf][h2 * 2 + 1]);
            }
        }
}

// ---------------------------------------------------------------------------
extern "C" void kernel_launch(void* const* d_in, const int* in_sizes, int n_in,
                              void* d_out, int out_size) {
    const float* q  = (const float*)d_in[0];
    const float* k  = (const float*)d_in[1];
    const float* v  = (const float*)d_in[2];
    const float* Wq = (const float*)d_in[3];
    const float* bq = (const float*)d_in[4];
    const float* Wk = (const float*)d_in[5];
    const float* bk = (const float*)d_in[6];
    const float* Wv = (const float*)d_in[7];
    const float* bv = (const float*)d_in[8];
    float* out = (float*)d_out;

    cudaFuncSetAttribute(proj_mma,   cudaFuncAttributeMaxDynamicSharedMemorySize, 65536);
    cudaFuncSetAttribute(scores_mma, cudaFuncAttributeMaxDynamicSharedMemorySize, 67584);
    cudaFuncSetAttribute(out_mma,    cudaFuncAttributeMaxDynamicSharedMemorySize, 49152);

    conv_w_all<<<3072, 256>>>(Wq, Wk, Wv);
    conv_xt_all<<<dim3(32, 32, 24), dim3(32, 8)>>>(q, k, v);
    proj_mma<<<dim3(8, 8, 24), 256, 65536>>>(bq, bk, bv);
    scores_mma<<<dim3(4, 8, NBH), 256, 67584>>>();
    merge_stats<<<dim3(4, NBH), 256>>>();
    vscale_kernel<<<16384, 256>>>();
    out_mma<<<dim3(8, NBH), 256, 49152>>>(out);
}

// round 14
// speedup vs baseline: 1.0455x; 1.0455x over previous
#include <cuda_runtime.h>
#include <cuda_fp16.h>
#include <math.h>
#include <stdint.h>

#define Bsz 8
#define Cc 1024
#define Ll 1024
#define Hh 16
#define Dk 64
#define NBH (Bsz*Hh)
#define SCALE 0.125f
#define NTB 8                       // number of t-blocks (128 each)

// ---------------------------------------------------------------------------
// Scratch (__device__ globals; no allocations allowed)
// ---------------------------------------------------------------------------
__device__ __half g_Whi[3][Cc*Cc];
__device__ __half g_xThi[3][(size_t)Bsz*Ll*Cc];   // [which][b][l][c]
__device__ __half g_qhi[(size_t)NBH*Ll*Dk];       // [bh][t][dk]
__device__ __half g_qlo[(size_t)NBH*Ll*Dk];
__device__ __half g_khi[(size_t)NBH*Ll*Dk];       // [bh][s][dk] (hi only)
__device__ __half g_vhi[(size_t)NBH*Dk*Ll];       // [bh][dk][s]
__device__ __half g_vlo[(size_t)NBH*Dk*Ll];       // used only pre-vscale
__device__ __half g_e [(size_t)NBH*Ll*Ll];        // 256 MB: E=exp(S) [bh][t][s]
__device__ float  g_pz[(size_t)NBH*NTB*Ll];       // partial colsum [bh][tb][s]
__device__ float  g_rz[NBH*Ll];                   // 1/z

#define SW128(o) ((uint32_t)(o) ^ ((((uint32_t)(o)) >> 3) & 0x70))

__device__ __forceinline__ uint32_t smem_u32(const void* p) {
    uint32_t a;
    asm("{ .reg .u64 t; cvta.to.shared.u64 t, %1; cvt.u32.u64 %0, t; }" : "=r"(a) : "l"(p));
    return a;
}
__device__ __forceinline__ void ldsm4(uint32_t* r, uint32_t addr) {
    asm volatile("ldmatrix.sync.aligned.m8n8.x4.shared.b16 {%0,%1,%2,%3}, [%4];"
                 : "=r"(r[0]), "=r"(r[1]), "=r"(r[2]), "=r"(r[3]) : "r"(addr));
}
__device__ __forceinline__ void mma16816(float* d, const uint32_t* a, const uint32_t* b) {
    asm volatile(
        "mma.sync.aligned.m16n8k16.row.col.f32.f16.f16.f32 "
        "{%0,%1,%2,%3}, {%4,%5,%6,%7}, {%8,%9}, {%0,%1,%2,%3};"
        : "+f"(d[0]), "+f"(d[1]), "+f"(d[2]), "+f"(d[3])
        : "r"(a[0]), "r"(a[1]), "r"(a[2]), "r"(a[3]), "r"(b[0]), "r"(b[1]));
}
__device__ __forceinline__ void cp16(uint32_t dst, const void* src) {
    asm volatile("cp.async.ca.shared.global [%0], [%1], 16;" :: "r"(dst), "l"(src));
}
#define CP_COMMIT() asm volatile("cp.async.commit_group;" ::: "memory")
#define CP_WAIT(n)  asm volatile("cp.async.wait_group %0;" :: "n"(n) : "memory")

// Async-load ROWS x 64 halfs (128B rows) into SW128-swizzled smem. 256 threads.
template <int ROWS>
__device__ __forceinline__ void load_tile_async(uint32_t dst, const __half* src,
                                                int stride_h, int tid) {
    #pragma unroll
    for (int i = 0; i < ROWS * 8 / 256; i++) {
        int idx = i * 256 + tid;
        int r = idx >> 3, cb = (idx & 7) * 16;
        cp16(dst + SW128(r * 128 + cb), (const char*)(src + (size_t)r * stride_h) + cb);
    }
}

// K=64 chunk of split-fp16 GEMM.
// NPROD=1: Ahi*Bhi.  NPROD=2: + Alo*Bhi.  NPROD=3: + Ahi*Blo.
template <int MF, int NF, int NPROD>
__device__ __forceinline__ void gemm_chunk(uint32_t saHi, uint32_t saLo,
                                           uint32_t sbHi, uint32_t sbLo,
                                           int m0, int n0, int lane,
                                           float acc[MF][NF][4]) {
    const int arow = lane & 15,                    acol8 = (lane >> 4) * 8;
    const int brow = (lane >> 4) * 8 + (lane & 7), bcol8 = ((lane >> 3) & 1) * 8;
    #pragma unroll
    for (int ks = 0; ks < 4; ks++) {
        const int k0 = ks * 16;
        uint32_t ahi[MF][4], alo[MF][4];
        #pragma unroll
        for (int mf = 0; mf < MF; mf++) {
            uint32_t off = SW128((m0 + mf * 16 + arow) * 128 + (k0 + acol8) * 2);
            ldsm4(ahi[mf], saHi + off);
            if (NPROD > 1) ldsm4(alo[mf], saLo + off);
        }
        uint32_t bhi[NF][2], blo[NF][2];
        #pragma unroll
        for (int p = 0; p < NF / 2; p++) {
            uint32_t off = SW128((n0 + p * 16 + brow) * 128 + (k0 + bcol8) * 2);
            uint32_t r[4];
            ldsm4(r, sbHi + off);
            bhi[p*2][0] = r[0]; bhi[p*2][1] = r[1];
            bhi[p*2+1][0] = r[2]; bhi[p*2+1][1] = r[3];
            if (NPROD > 2) {
                ldsm4(r, sbLo + off);
                blo[p*2][0] = r[0]; blo[p*2][1] = r[1];
                blo[p*2+1][0] = r[2]; blo[p*2+1][1] = r[3];
            }
        }
        #pragma unroll
        for (int mf = 0; mf < MF; mf++)
            #pragma unroll
            for (int nf = 0; nf < NF; nf++) {
                mma16816(acc[mf][nf], ahi[mf], bhi[nf]);
                if (NPROD > 1) mma16816(acc[mf][nf], alo[mf], bhi[nf]);
                if (NPROD > 2) mma16816(acc[mf][nf], ahi[mf], blo[nf]);
            }
    }
}

// ---------------------------------------------------------------------------
// Conversions (hi-only weights)
// ---------------------------------------------------------------------------
__global__ __launch_bounds__(256) void conv_w_all(const float* __restrict__ W0,
                                                  const float* __restrict__ W1,
                                                  const float* __restrict__ W2) {
    const int which = blockIdx.x >> 10;
    const float* W = (which == 0) ? W0 : (which == 1 ? W1 : W2);
    int i = ((blockIdx.x & 1023) * 256 + threadIdx.x) * 4;
    float4 v = *(const float4*)(W + i);
    __half2* H = (__half2*)(g_Whi[which] + i);
    H[0] = __halves2half2(__float2half_rn(v.x), __float2half_rn(v.y));
    H[1] = __halves2half2(__float2half_rn(v.z), __float2half_rn(v.w));
}

__global__ __launch_bounds__(256) void conv_xt_all(const float* __restrict__ x0,
                                                   const float* __restrict__ x1,
                                                   const float* __restrict__ x2) {
    __shared__ float tile[32][33];
    const int which = blockIdx.z >> 3, b = blockIdx.z & 7;
    const float* x = (which == 0) ? x0 : (which == 1 ? x1 : x2);
    const int c0 = blockIdx.y * 32, l0 = blockIdx.x * 32;
    const int tx = threadIdx.x, ty = threadIdx.y;
    const float* xb = x + (size_t)b * Cc * Ll;
    #pragma unroll
    for (int i = 0; i < 4; i++)
        tile[ty + i * 8][tx] = xb[(size_t)(c0 + ty + i * 8) * Ll + l0 + tx];
    __syncthreads();
    #pragma unroll
    for (int i = 0; i < 4; i++) {
        float vv = tile[tx][ty + i * 8];
        size_t o = (size_t)b * Ll * Cc + (size_t)(l0 + ty + i * 8) * Cc + c0 + tx;
        g_xThi[which][o] = __float2half_rn(vv);
    }
}

// ---------------------------------------------------------------------------
// Projection (all 3 in one launch): Y[o,l] = sum_c W[o,c] xT[l,c] + bias[o].
// Plain fp16 GEMM. 2-stage double-buffer (stage=32KB).
// q: hi+lo out; k: hi only; v: hi+lo out.
// ---------------------------------------------------------------------------
__global__ __launch_bounds__(256) void proj_mma(const float* __restrict__ bias0,
                                                const float* __restrict__ bias1,
                                                const float* __restrict__ bias2) {
    extern __shared__ char smem[];
    uint32_t sb = smem_u32(smem);
    const int tid = threadIdx.x, w = tid >> 5, lane = tid & 31;
    const int wm = w >> 1, wn = w & 1;
    const int which = blockIdx.z >> 3, b = blockIdx.z & 7;
    const int o0 = blockIdx.y * 128, l0 = blockIdx.x * 128;
    const float* bias = (which == 0) ? bias0 : (which == 1 ? bias1 : bias2);

    const __half* Whi = g_Whi[which] + (size_t)o0 * Cc;
    const __half* Xhi = g_xThi[which] + (size_t)b * Ll * Cc + (size_t)l0 * Cc;

    auto AH = [&](int st) { return sb + st * 32768; };
    auto BH = [&](int st) { return sb + st * 32768 + 16384; };

    load_tile_async<128>(AH(0), Whi, Cc, tid);
    load_tile_async<128>(BH(0), Xhi, Cc, tid);
    CP_COMMIT();

    float acc[2][8][4] = {};
    for (int it = 0; it < 16; it++) {
        if (it < 15) {
            const int c1 = (it + 1) * 64, st = (it + 1) & 1;
            load_tile_async<128>(AH(st), Whi + c1, Cc, tid);
            load_tile_async<128>(BH(st), Xhi + c1, Cc, tid);
            CP_COMMIT();
            CP_WAIT(1);
        } else {
            CP_WAIT(0);
        }
        __syncthreads();
        const int st = it & 1;
        gemm_chunk<2, 8, 1>(AH(st), AH(st), BH(st), BH(st),
                            wm * 32, wn * 64, lane, acc);
        __syncthreads();
    }

    const int gid = lane >> 2, tid4 = lane & 3;
    if (which < 2) {
        __half* Ls = (__half*)smem;                 // 128 x 128 halfs
        __half* Hp = (which == 0 ? g_qhi : g_khi);
        const int hh0 = o0 >> 6;
        const int npass = (which == 0) ? 2 : 1;     // k is hi-only
        for (int pass = 0; pass < npass; pass++) {
            #pragma unroll
            for (int mf = 0; mf < 2; mf++)
                #pragma unroll
                for (int h2 = 0; h2 < 2; h2++) {
                    const int o = wm * 32 + mf * 16 + gid + h2 * 8;
                    const float bi = bias[o0 + o];
                    #pragma unroll
                    for (int nf = 0; nf < 8; nf++)
                        #pragma unroll
                        for (int j = 0; j < 2; j++) {
                            const int l = wn * 64 + nf * 8 + tid4 * 2 + j;
                            float v = acc[mf][nf][h2 * 2 + j] + bi;
                            __half hi = __float2half_rn(v);
                            Ls[l * 128 + o] = pass == 0 ? hi
                                : __float2half_rn(v - __half2float(hi));
                        }
                }
            __syncthreads();
            __half* P = pass == 0 ? Hp : g_qlo;
            #pragma unroll
            for (int it = 0; it < 8; it++) {
                int cid = it * 256 + tid;
                int l_loc = cid >> 4, hh_loc = (cid >> 3) & 1, c16 = cid & 7;
                uint4 vv = *(uint4*)(Ls + l_loc * 128 + hh_loc * 64 + c16 * 8);
                size_t off = ((size_t)(b * Hh + hh0 + hh_loc) * Ll + l0 + l_loc) * Dk + c16 * 8;
                *(uint4*)(P + off) = vv;
            }
            __syncthreads();
        }
    } else {
        #pragma unroll
        for (int mf = 0; mf < 2; mf++)
            #pragma unroll
            for (int h2 = 0; h2 < 2; h2++) {
                const int o = o0 + wm * 32 + mf * 16 + gid + h2 * 8;
                const float bi = bias[o];
                const int hh = o >> 6, dk = o & 63;
                #pragma unroll
                for (int nf = 0; nf < 8; nf++) {
                    const int l = l0 + wn * 64 + nf * 8 + tid4 * 2;
                    float v0 = acc[mf][nf][h2 * 2 + 0] + bi;
                    float v1 = acc[mf][nf][h2 * 2 + 1] + bi;
                    __half hi0 = __float2half_rn(v0);
                    __half lo0 = __float2half_rn(v0 - __half2float(hi0));
                    __half hi1 = __float2half_rn(v1);
                    __half lo1 = __float2half_rn(v1 - __half2float(hi1));
                    size_t off = ((size_t)(b * Hh + hh) * Dk + dk) * Ll + l;
                    *(__half2*)(g_vhi + off) = __halves2half2(hi0, hi1);
                    *(__half2*)(g_vlo + off) = __halves2half2(lo0, lo1);
                }
            }
    }
}

// ---------------------------------------------------------------------------
// Scores (R12 version): E[t,s] = exp(SCALE * sum_c Q[t,c] K[s,c]) as fp16,
// plus per-block column partial sums. Block 128t x 128s, one tile per block.
// 2-product: Qhi*Khi + Qlo*Khi.
// ---------------------------------------------------------------------------
__global__ __launch_bounds__(256) void scores_mma() {
    extern __shared__ char smem[];
    const int AH = 0, AL = 16384, BH = 32768;
    uint32_t sb = smem_u32(smem);
    const int tid = threadIdx.x, w = tid >> 5, lane = tid & 31;
    const int wm = w >> 1, wn = w & 1;
    const int bh = blockIdx.z, t0 = blockIdx.y * 128, s0 = blockIdx.x * 128;

    load_tile_async<128>(sb + AH, g_qhi + ((size_t)bh * Ll + t0) * Dk, Dk, tid);
    load_tile_async<128>(sb + AL, g_qlo + ((size_t)bh * Ll + t0) * Dk, Dk, tid);
    load_tile_async<128>(sb + BH, g_khi + ((size_t)bh * Ll + s0) * Dk, Dk, tid);
    CP_COMMIT();
    CP_WAIT(0);
    __syncthreads();

    float acc[2][8][4] = {};
    gemm_chunk<2, 8, 2>(sb + AH, sb + AL, sb + BH, sb + BH,
                        wm * 32, wn * 64, lane, acc);

    // Exponentiate in place (bounded logits: no max subtraction needed).
    #pragma unroll
    for (int mf = 0; mf < 2; mf++)
        #pragma unroll
        for (int nf = 0; nf < 8; nf++)
            #pragma unroll
            for (int e = 0; e < 4; e++)
                acc[mf][nf][e] = __expf(acc[mf][nf][e] * SCALE);

    const int gid = lane >> 2, tid4 = lane & 3;

    // Column partial sums over this block's 128 t: add-only reduction.
    __syncthreads();                       // tiles dead; reuse smem
    float* smZ = (float*)smem;             // [128 s][4 wm]
    #pragma unroll
    for (int nf = 0; nf < 8; nf++)
        #pragma unroll
        for (int j = 0; j < 2; j++) {
            float z = acc[0][nf][j] + acc[0][nf][2 + j]
                    + acc[1][nf][j] + acc[1][nf][2 + j];
            #pragma unroll
            for (int off = 4; off <= 16; off <<= 1)
                z += __shfl_xor_sync(0xffffffffu, z, off);
            if (gid == 0)
                smZ[(wn * 64 + nf * 8 + tid4 * 2 + j) * 4 + wm] = z;
        }
    __syncthreads();
    if (tid < 128) {
        float z = smZ[tid * 4] + smZ[tid * 4 + 1] + smZ[tid * 4 + 2] + smZ[tid * 4 + 3];
        g_pz[((size_t)bh * NTB + blockIdx.y) * Ll + s0 + tid] = z;
    }

    // Write E (fp16).
    __half* Eb = g_e + (size_t)bh * Ll * Ll;
    #pragma unroll
    for (int mf = 0; mf < 2; mf++)
        #pragma unroll
        for (int h2 = 0; h2 < 2; h2++) {
            const int t = t0 + wm * 32 + mf * 16 + gid + h2 * 8;
            __half* rowp = Eb + (size_t)t * Ll;
            #pragma unroll
            for (int nf = 0; nf < 8; nf++) {
                const int s = s0 + wn * 64 + nf * 8 + tid4 * 2;
                *(__half2*)(rowp + s) =
                    __halves2half2(__float2half_rn(acc[mf][nf][h2 * 2]),
                                   __float2half_rn(acc[mf][nf][h2 * 2 + 1]));
            }
        }
}

// ---------------------------------------------------------------------------
// Merge partials -> rz = 1/z.  (adds only)
// ---------------------------------------------------------------------------
__global__ __launch_bounds__(256) void merge_stats() {
    const int bh = blockIdx.y;
    const int s = blockIdx.x * 256 + threadIdx.x;
    float z = 0.f;
    #pragma unroll
    for (int tb = 0; tb < NTB; tb++)
        z += g_pz[((size_t)bh * NTB + tb) * Ll + s];
    g_rz[bh * Ll + s] = 1.f / z;
}

// ---------------------------------------------------------------------------
// V pre-scale: V'hi = fp16((vhi+vlo) * rz[s]); lo no longer used downstream.
// ---------------------------------------------------------------------------
__global__ __launch_bounds__(256) void vscale_kernel() {
    int gid = blockIdx.x * 256 + threadIdx.x;      // half2 index
    int sp = (gid & 511) * 2;
    int bh = gid >> 15;                            // /(64 dk * 512 half2)
    __half2 h = ((__half2*)g_vhi)[gid];
    __half2 l = ((__half2*)g_vlo)[gid];
    float r0 = g_rz[bh * Ll + sp], r1 = g_rz[bh * Ll + sp + 1];
    float v0 = (__low2float(h)  + __low2float(l))  * r0;
    float v1 = (__high2float(h) + __high2float(l)) * r1;
    ((__half2*)g_vhi)[gid] =
        __halves2half2(__float2half_rn(v0), __float2half_rn(v1));
}

// ---------------------------------------------------------------------------
// Output: out[c,t] = sum_s E[t,s] V'[c,s].  Single-product double-buffered
// GEMM. Block 64(c) x 128(t); 8 warps (2m x 4n); 16 s-chunks of 64.
// stage = [E 16KB][Vhi 8KB] x2 = 48KB
// ---------------------------------------------------------------------------
__global__ __launch_bounds__(256) void out_mma(float* __restrict__ out) {
    extern __shared__ char smem[];
    uint32_t sb = smem_u32(smem);
    const int tid = threadIdx.x, w = tid >> 5, lane = tid & 31;
    const int wm = w >> 2, wn = w & 3;
    const int bh = blockIdx.y, t0 = blockIdx.x * 128;

    const __half* Ep = g_e + (size_t)bh * Ll * Ll + (size_t)t0 * Ll;
    const __half* Vh = g_vhi + (size_t)bh * Dk * Ll;

    auto EH = [&](int st) { return sb + st * 24576; };
    auto VH = [&](int st) { return sb + st * 24576 + 16384; };

    load_tile_async<128>(EH(0), Ep, Ll, tid);
    load_tile_async<64>(VH(0), Vh, Ll, tid);
    CP_COMMIT();

    float acc[2][4][4] = {};
    for (int it = 0; it < 16; it++) {
        if (it < 15) {
            const int s1 = (it + 1) * 64, st = (it + 1) & 1;
            load_tile_async<128>(EH(st), Ep + s1, Ll, tid);
            load_tile_async<64>(VH(st), Vh + s1, Ll, tid);
            CP_COMMIT();
            CP_WAIT(1);
        } else {
            CP_WAIT(0);
        }
        __syncthreads();
        const int st = it & 1;
        gemm_chunk<2, 4, 1>(VH(st), VH(st), EH(st), EH(st),
                            wm * 32, wn * 32, lane, acc);
        __syncthreads();
    }

    float* ob = out + (size_t)bh * Dk * Ll;
    const int gid = lane >> 2, tid4 = lane & 3;
    #pragma unroll
    for (int mf = 0; mf < 2; mf++)
        #pragma unroll
        for (int h2 = 0; h2 < 2; h2++) {
            const int c = wm * 32 + mf * 16 + gid + h2 * 8;
            #pragma unroll
            for (int nf = 0; nf < 4; nf++) {
                const int t = t0 + wn * 32 + nf * 8 + tid4 * 2;
                *(float2*)(ob + (size_t)c * Ll + t) =
                    make_float2(acc[mf][nf][h2 * 2], acc[mf][nf][h2 * 2 + 1]);
            }
        }
}

// ---------------------------------------------------------------------------
extern "C" void kernel_launch(void* const* d_in, const int* in_sizes, int n_in,
                              void* d_out, int out_size) {
    const float* q  = (const float*)d_in[0];
    const float* k  = (const float*)d_in[1];
    const float* v  = (const float*)d_in[2];
    const float* Wq = (const float*)d_in[3];
    const float* bq = (const float*)d_in[4];
    const float* Wk = (const float*)d_in[5];
    const float* bk = (const float*)d_in[6];
    const float* Wv = (const float*)d_in[7];
    const float* bv = (const float*)d_in[8];
    float* out = (float*)d_out;

    cudaFuncSetAttribute(proj_mma,   cudaFuncAttributeMaxDynamicSharedMemorySize, 65536);
    cudaFuncSetAttribute(scores_mma, cudaFuncAttributeMaxDynamicSharedMemorySize, 49152);
    cudaFuncSetAttribute(out_mma,    cudaFuncAttributeMaxDynamicSharedMemorySize, 49152);

    conv_w_all<<<3072, 256>>>(Wq, Wk, Wv);
    conv_xt_all<<<dim3(32, 32, 24), dim3(32, 8)>>>(q, k, v);
    proj_mma<<<dim3(8, 8, 24), 256, 65536>>>(bq, bk, bv);
    scores_mma<<<dim3(8, 8, NBH), 256, 49152>>>();
    merge_stats<<<dim3(4, NBH), 256>>>();
    vscale_kernel<<<16384, 256>>>();
    out_mma<<<dim3(8, NBH), 256, 49152>>>(out);
}

// round 15
// speedup vs baseline: 1.1244x; 1.0754x over previous
#include <cuda_runtime.h>
#include <cuda_fp16.h>
#include <math.h>
#include <stdint.h>

#define Bsz 8
#define Cc 1024
#define Ll 1024
#define Hh 16
#define Dk 64
#define NBH (Bsz*Hh)
#define SCALE 0.125f
#define NTB 8                       // number of t-blocks (128 each)

// ---------------------------------------------------------------------------
// Scratch (__device__ globals; no allocations allowed)
// ---------------------------------------------------------------------------
__device__ __half g_Whi[3][Cc*Cc];
__device__ __half g_xThi[3][(size_t)Bsz*Ll*Cc];   // [which][b][l][c]
__device__ __half g_qhi[(size_t)NBH*Ll*Dk];       // [bh][t][dk] (hi only)
__device__ __half g_khi[(size_t)NBH*Ll*Dk];       // [bh][s][dk] (hi only)
__device__ __half g_vhi[(size_t)NBH*Dk*Ll];       // [bh][dk][s]
__device__ __half g_vlo[(size_t)NBH*Dk*Ll];       // used only pre-vscale
__device__ __half g_e [(size_t)NBH*Ll*Ll];        // 256 MB: E=exp(S) [bh][t][s]
__device__ float  g_pz[(size_t)NBH*NTB*Ll];       // partial colsum [bh][tb][s]
__device__ float  g_rz[NBH*Ll];                   // 1/z

#define SW128(o) ((uint32_t)(o) ^ ((((uint32_t)(o)) >> 3) & 0x70))

__device__ __forceinline__ uint32_t smem_u32(const void* p) {
    uint32_t a;
    asm("{ .reg .u64 t; cvta.to.shared.u64 t, %1; cvt.u32.u64 %0, t; }" : "=r"(a) : "l"(p));
    return a;
}
__device__ __forceinline__ void ldsm4(uint32_t* r, uint32_t addr) {
    asm volatile("ldmatrix.sync.aligned.m8n8.x4.shared.b16 {%0,%1,%2,%3}, [%4];"
                 : "=r"(r[0]), "=r"(r[1]), "=r"(r[2]), "=r"(r[3]) : "r"(addr));
}
__device__ __forceinline__ void mma16816(float* d, const uint32_t* a, const uint32_t* b) {
    asm volatile(
        "mma.sync.aligned.m16n8k16.row.col.f32.f16.f16.f32 "
        "{%0,%1,%2,%3}, {%4,%5,%6,%7}, {%8,%9}, {%0,%1,%2,%3};"
        : "+f"(d[0]), "+f"(d[1]), "+f"(d[2]), "+f"(d[3])
        : "r"(a[0]), "r"(a[1]), "r"(a[2]), "r"(a[3]), "r"(b[0]), "r"(b[1]));
}
__device__ __forceinline__ void cp16(uint32_t dst, const void* src) {
    asm volatile("cp.async.ca.shared.global [%0], [%1], 16;" :: "r"(dst), "l"(src));
}
#define CP_COMMIT() asm volatile("cp.async.commit_group;" ::: "memory")
#define CP_WAIT(n)  asm volatile("cp.async.wait_group %0;" :: "n"(n) : "memory")

// Async-load ROWS x 64 halfs (128B rows) into SW128-swizzled smem. 256 threads.
template <int ROWS>
__device__ __forceinline__ void load_tile_async(uint32_t dst, const __half* src,
                                                int stride_h, int tid) {
    #pragma unroll
    for (int i = 0; i < ROWS * 8 / 256; i++) {
        int idx = i * 256 + tid;
        int r = idx >> 3, cb = (idx & 7) * 16;
        cp16(dst + SW128(r * 128 + cb), (const char*)(src + (size_t)r * stride_h) + cb);
    }
}

// K=64 chunk of split-fp16 GEMM.
// NPROD=1: Ahi*Bhi.  NPROD=2: + Alo*Bhi.  NPROD=3: + Ahi*Blo.
template <int MF, int NF, int NPROD>
__device__ __forceinline__ void gemm_chunk(uint32_t saHi, uint32_t saLo,
                                           uint32_t sbHi, uint32_t sbLo,
                                           int m0, int n0, int lane,
                                           float acc[MF][NF][4]) {
    const int arow = lane & 15,                    acol8 = (lane >> 4) * 8;
    const int brow = (lane >> 4) * 8 + (lane & 7), bcol8 = ((lane >> 3) & 1) * 8;
    #pragma unroll
    for (int ks = 0; ks < 4; ks++) {
        const int k0 = ks * 16;
        uint32_t ahi[MF][4], alo[MF][4];
        #pragma unroll
        for (int mf = 0; mf < MF; mf++) {
            uint32_t off = SW128((m0 + mf * 16 + arow) * 128 + (k0 + acol8) * 2);
            ldsm4(ahi[mf], saHi + off);
            if (NPROD > 1) ldsm4(alo[mf], saLo + off);
        }
        uint32_t bhi[NF][2], blo[NF][2];
        #pragma unroll
        for (int p = 0; p < NF / 2; p++) {
            uint32_t off = SW128((n0 + p * 16 + brow) * 128 + (k0 + bcol8) * 2);
            uint32_t r[4];
            ldsm4(r, sbHi + off);
            bhi[p*2][0] = r[0]; bhi[p*2][1] = r[1];
            bhi[p*2+1][0] = r[2]; bhi[p*2+1][1] = r[3];
            if (NPROD > 2) {
                ldsm4(r, sbLo + off);
                blo[p*2][0] = r[0]; blo[p*2][1] = r[1];
                blo[p*2+1][0] = r[2]; blo[p*2+1][1] = r[3];
            }
        }
        #pragma unroll
        for (int mf = 0; mf < MF; mf++)
            #pragma unroll
            for (int nf = 0; nf < NF; nf++) {
                mma16816(acc[mf][nf], ahi[mf], bhi[nf]);
                if (NPROD > 1) mma16816(acc[mf][nf], alo[mf], bhi[nf]);
                if (NPROD > 2) mma16816(acc[mf][nf], ahi[mf], blo[nf]);
            }
    }
}

// ---------------------------------------------------------------------------
// Conversions (hi-only weights)
// ---------------------------------------------------------------------------
__global__ __launch_bounds__(256) void conv_w_all(const float* __restrict__ W0,
                                                  const float* __restrict__ W1,
                                                  const float* __restrict__ W2) {
    const int which = blockIdx.x >> 10;
    const float* W = (which == 0) ? W0 : (which == 1 ? W1 : W2);
    int i = ((blockIdx.x & 1023) * 256 + threadIdx.x) * 4;
    float4 v = *(const float4*)(W + i);
    __half2* H = (__half2*)(g_Whi[which] + i);
    H[0] = __halves2half2(__float2half_rn(v.x), __float2half_rn(v.y));
    H[1] = __halves2half2(__float2half_rn(v.z), __float2half_rn(v.w));
}

__global__ __launch_bounds__(256) void conv_xt_all(const float* __restrict__ x0,
                                                   const float* __restrict__ x1,
                                                   const float* __restrict__ x2) {
    __shared__ float tile[32][33];
    const int which = blockIdx.z >> 3, b = blockIdx.z & 7;
    const float* x = (which == 0) ? x0 : (which == 1 ? x1 : x2);
    const int c0 = blockIdx.y * 32, l0 = blockIdx.x * 32;
    const int tx = threadIdx.x, ty = threadIdx.y;
    const float* xb = x + (size_t)b * Cc * Ll;
    #pragma unroll
    for (int i = 0; i < 4; i++)
        tile[ty + i * 8][tx] = xb[(size_t)(c0 + ty + i * 8) * Ll + l0 + tx];
    __syncthreads();
    #pragma unroll
    for (int i = 0; i < 4; i++) {
        float vv = tile[tx][ty + i * 8];
        size_t o = (size_t)b * Ll * Cc + (size_t)(l0 + ty + i * 8) * Cc + c0 + tx;
        g_xThi[which][o] = __float2half_rn(vv);
    }
}

// ---------------------------------------------------------------------------
// Projection (all 3 in one launch): Y[o,l] = sum_c W[o,c] xT[l,c] + bias[o].
// Plain fp16 GEMM. 2-stage double-buffer (stage=32KB).
// q: hi only; k: hi only; v: hi+lo out.
// ---------------------------------------------------------------------------
__global__ __launch_bounds__(256) void proj_mma(const float* __restrict__ bias0,
                                                const float* __restrict__ bias1,
                                                const float* __restrict__ bias2) {
    extern __shared__ char smem[];
    uint32_t sb = smem_u32(smem);
    const int tid = threadIdx.x, w = tid >> 5, lane = tid & 31;
    const int wm = w >> 1, wn = w & 1;
    const int which = blockIdx.z >> 3, b = blockIdx.z & 7;
    const int o0 = blockIdx.y * 128, l0 = blockIdx.x * 128;
    const float* bias = (which == 0) ? bias0 : (which == 1 ? bias1 : bias2);

    const __half* Whi = g_Whi[which] + (size_t)o0 * Cc;
    const __half* Xhi = g_xThi[which] + (size_t)b * Ll * Cc + (size_t)l0 * Cc;

    auto AH = [&](int st) { return sb + st * 32768; };
    auto BH = [&](int st) { return sb + st * 32768 + 16384; };

    load_tile_async<128>(AH(0), Whi, Cc, tid);
    load_tile_async<128>(BH(0), Xhi, Cc, tid);
    CP_COMMIT();

    float acc[2][8][4] = {};
    for (int it = 0; it < 16; it++) {
        if (it < 15) {
            const int c1 = (it + 1) * 64, st = (it + 1) & 1;
            load_tile_async<128>(AH(st), Whi + c1, Cc, tid);
            load_tile_async<128>(BH(st), Xhi + c1, Cc, tid);
            CP_COMMIT();
            CP_WAIT(1);
        } else {
            CP_WAIT(0);
        }
        __syncthreads();
        const int st = it & 1;
        gemm_chunk<2, 8, 1>(AH(st), AH(st), BH(st), BH(st),
                            wm * 32, wn * 64, lane, acc);
        __syncthreads();
    }

    const int gid = lane >> 2, tid4 = lane & 3;
    if (which < 2) {
        // Single hi-only pass through smem, coalesced flush as [bh][l][dk].
        __half* Ls = (__half*)smem;                 // 128 x 128 halfs
        __half* Hp = (which == 0 ? g_qhi : g_khi);
        const int hh0 = o0 >> 6;
        #pragma unroll
        for (int mf = 0; mf < 2; mf++)
            #pragma unroll
            for (int h2 = 0; h2 < 2; h2++) {
                const int o = wm * 32 + mf * 16 + gid + h2 * 8;
                const float bi = bias[o0 + o];
                #pragma unroll
                for (int nf = 0; nf < 8; nf++)
                    #pragma unroll
                    for (int j = 0; j < 2; j++) {
                        const int l = wn * 64 + nf * 8 + tid4 * 2 + j;
                        Ls[l * 128 + o] =
                            __float2half_rn(acc[mf][nf][h2 * 2 + j] + bi);
                    }
            }
        __syncthreads();
        #pragma unroll
        for (int it = 0; it < 8; it++) {
            int cid = it * 256 + tid;
            int l_loc = cid >> 4, hh_loc = (cid >> 3) & 1, c16 = cid & 7;
            uint4 vv = *(uint4*)(Ls + l_loc * 128 + hh_loc * 64 + c16 * 8);
            size_t off = ((size_t)(b * Hh + hh0 + hh_loc) * Ll + l0 + l_loc) * Dk + c16 * 8;
            *(uint4*)(Hp + off) = vv;
        }
        __syncthreads();
    } else {
        #pragma unroll
        for (int mf = 0; mf < 2; mf++)
            #pragma unroll
            for (int h2 = 0; h2 < 2; h2++) {
                const int o = o0 + wm * 32 + mf * 16 + gid + h2 * 8;
                const float bi = bias[o];
                const int hh = o >> 6, dk = o & 63;
                #pragma unroll
                for (int nf = 0; nf < 8; nf++) {
                    const int l = l0 + wn * 64 + nf * 8 + tid4 * 2;
                    float v0 = acc[mf][nf][h2 * 2 + 0] + bi;
                    float v1 = acc[mf][nf][h2 * 2 + 1] + bi;
                    __half hi0 = __float2half_rn(v0);
                    __half lo0 = __float2half_rn(v0 - __half2float(hi0));
                    __half hi1 = __float2half_rn(v1);
                    __half lo1 = __float2half_rn(v1 - __half2float(hi1));
                    size_t off = ((size_t)(b * Hh + hh) * Dk + dk) * Ll + l;
                    *(__half2*)(g_vhi + off) = __halves2half2(hi0, hi1);
                    *(__half2*)(g_vlo + off) = __halves2half2(lo0, lo1);
                }
            }
    }
}

// ---------------------------------------------------------------------------
// Scores: E[t,s] = exp(SCALE * sum_c Q[t,c] K[s,c]) as fp16, plus per-block
// column partial sums. Block 128t x 128s, one tile per block.
// Pure fp16 single product (Q hi, K hi). smem: [QH 16K][KH 16K] + smZ reuse.
// ---------------------------------------------------------------------------
__global__ __launch_bounds__(256) void scores_mma() {
    extern __shared__ char smem[];
    const int AH = 0, BH = 16384;
    uint32_t sb = smem_u32(smem);
    const int tid = threadIdx.x, w = tid >> 5, lane = tid & 31;
    const int wm = w >> 1, wn = w & 1;
    const int bh = blockIdx.z, t0 = blockIdx.y * 128, s0 = blockIdx.x * 128;

    load_tile_async<128>(sb + AH, g_qhi + ((size_t)bh * Ll + t0) * Dk, Dk, tid);
    load_tile_async<128>(sb + BH, g_khi + ((size_t)bh * Ll + s0) * Dk, Dk, tid);
    CP_COMMIT();
    CP_WAIT(0);
    __syncthreads();

    float acc[2][8][4] = {};
    gemm_chunk<2, 8, 1>(sb + AH, sb + AH, sb + BH, sb + BH,
                        wm * 32, wn * 64, lane, acc);

    // Exponentiate in place (bounded logits: no max subtraction needed).
    #pragma unroll
    for (int mf = 0; mf < 2; mf++)
        #pragma unroll
        for (int nf = 0; nf < 8; nf++)
            #pragma unroll
            for (int e = 0; e < 4; e++)
                acc[mf][nf][e] = __expf(acc[mf][nf][e] * SCALE);

    const int gid = lane >> 2, tid4 = lane & 3;

    // Column partial sums over this block's 128 t: add-only reduction.
    __syncthreads();                       // tiles dead; reuse smem
    float* smZ = (float*)smem;             // [128 s][4 wm]
    #pragma unroll
    for (int nf = 0; nf < 8; nf++)
        #pragma unroll
        for (int j = 0; j < 2; j++) {
            float z = acc[0][nf][j] + acc[0][nf][2 + j]
                    + acc[1][nf][j] + acc[1][nf][2 + j];
            #pragma unroll
            for (int off = 4; off <= 16; off <<= 1)
                z += __shfl_xor_sync(0xffffffffu, z, off);
            if (gid == 0)
                smZ[(wn * 64 + nf * 8 + tid4 * 2 + j) * 4 + wm] = z;
        }
    __syncthreads();
    if (tid < 128) {
        float z = smZ[tid * 4] + smZ[tid * 4 + 1] + smZ[tid * 4 + 2] + smZ[tid * 4 + 3];
        g_pz[((size_t)bh * NTB + blockIdx.y) * Ll + s0 + tid] = z;
    }

    // Write E (fp16).
    __half* Eb = g_e + (size_t)bh * Ll * Ll;
    #pragma unroll
    for (int mf = 0; mf < 2; mf++)
        #pragma unroll
        for (int h2 = 0; h2 < 2; h2++) {
            const int t = t0 + wm * 32 + mf * 16 + gid + h2 * 8;
            __half* rowp = Eb + (size_t)t * Ll;
            #pragma unroll
            for (int nf = 0; nf < 8; nf++) {
                const int s = s0 + wn * 64 + nf * 8 + tid4 * 2;
                *(__half2*)(rowp + s) =
                    __halves2half2(__float2half_rn(acc[mf][nf][h2 * 2]),
                                   __float2half_rn(acc[mf][nf][h2 * 2 + 1]));
            }
        }
}

// ---------------------------------------------------------------------------
// Merge partials -> rz = 1/z.  (adds only)
// ---------------------------------------------------------------------------
__global__ __launch_bounds__(256) void merge_stats() {
    const int bh = blockIdx.y;
    const int s = blockIdx.x * 256 + threadIdx.x;
    float z = 0.f;
    #pragma unroll
    for (int tb = 0; tb < NTB; tb++)
        z += g_pz[((size_t)bh * NTB + tb) * Ll + s];
    g_rz[bh * Ll + s] = 1.f / z;
}

// ---------------------------------------------------------------------------
// V pre-scale: V'hi = fp16((vhi+vlo) * rz[s]); lo no longer used downstream.
// ---------------------------------------------------------------------------
__global__ __launch_bounds__(256) void vscale_kernel() {
    int gid = blockIdx.x * 256 + threadIdx.x;      // half2 index
    int sp = (gid & 511) * 2;
    int bh = gid >> 15;                            // /(64 dk * 512 half2)
    __half2 h = ((__half2*)g_vhi)[gid];
    __half2 l = ((__half2*)g_vlo)[gid];
    float r0 = g_rz[bh * Ll + sp], r1 = g_rz[bh * Ll + sp + 1];
    float v0 = (__low2float(h)  + __low2float(l))  * r0;
    float v1 = (__high2float(h) + __high2float(l)) * r1;
    ((__half2*)g_vhi)[gid] =
        __halves2half2(__float2half_rn(v0), __float2half_rn(v1));
}

// ---------------------------------------------------------------------------
// Output: out[c,t] = sum_s E[t,s] V'[c,s].  Single-product double-buffered
// GEMM. Block 64(c) x 128(t); 8 warps (2m x 4n); 16 s-chunks of 64.
// stage = [E 16KB][Vhi 8KB] x2 = 48KB
// ---------------------------------------------------------------------------
__global__ __launch_bounds__(256) void out_mma(float* __restrict__ out) {
    extern __shared__ char smem[];
    uint32_t sb = smem_u32(smem);
    const int tid = threadIdx.x, w = tid >> 5, lane = tid & 31;
    const int wm = w >> 2, wn = w & 3;
    const int bh = blockIdx.y, t0 = blockIdx.x * 128;

    const __half* Ep = g_e + (size_t)bh * Ll * Ll + (size_t)t0 * Ll;
    const __half* Vh = g_vhi + (size_t)bh * Dk * Ll;

    auto EH = [&](int st) { return sb + st * 24576; };
    auto VH = [&](int st) { return sb + st * 24576 + 16384; };

    load_tile_async<128>(EH(0), Ep, Ll, tid);
    load_tile_async<64>(VH(0), Vh, Ll, tid);
    CP_COMMIT();

    float acc[2][4][4] = {};
    for (int it = 0; it < 16; it++) {
        if (it < 15) {
            const int s1 = (it + 1) * 64, st = (it + 1) & 1;
            load_tile_async<128>(EH(st), Ep + s1, Ll, tid);
            load_tile_async<64>(VH(st), Vh + s1, Ll, tid);
            CP_COMMIT();
            CP_WAIT(1);
        } else {
            CP_WAIT(0);
        }
        __syncthreads();
        const int st = it & 1;
        gemm_chunk<2, 4, 1>(VH(st), VH(st), EH(st), EH(st),
                            wm * 32, wn * 32, lane, acc);
        __syncthreads();
    }

    float* ob = out + (size_t)bh * Dk * Ll;
    const int gid = lane >> 2, tid4 = lane & 3;
    #pragma unroll
    for (int mf = 0; mf < 2; mf++)
        #pragma unroll
        for (int h2 = 0; h2 < 2; h2++) {
            const int c = wm * 32 + mf * 16 + gid + h2 * 8;
            #pragma unroll
            for (int nf = 0; nf < 4; nf++) {
                const int t = t0 + wn * 32 + nf * 8 + tid4 * 2;
                *(float2*)(ob + (size_t)c * Ll + t) =
                    make_float2(acc[mf][nf][h2 * 2], acc[mf][nf][h2 * 2 + 1]);
            }
        }
}

// ---------------------------------------------------------------------------
extern "C" void kernel_launch(void* const* d_in, const int* in_sizes, int n_in,
                              void* d_out, int out_size) {
    const float* q  = (const float*)d_in[0];
    const float* k  = (const float*)d_in[1];
    const float* v  = (const float*)d_in[2];
    const float* Wq = (const float*)d_in[3];
    const float* bq = (const float*)d_in[4];
    const float* Wk = (const float*)d_in[5];
    const float* bk = (const float*)d_in[6];
    const float* Wv = (const float*)d_in[7];
    const float* bv = (const float*)d_in[8];
    float* out = (float*)d_out;

    cudaFuncSetAttribute(proj_mma,   cudaFuncAttributeMaxDynamicSharedMemorySize, 65536);
    cudaFuncSetAttribute(scores_mma, cudaFuncAttributeMaxDynamicSharedMemorySize, 32768);
    cudaFuncSetAttribute(out_mma,    cudaFuncAttributeMaxDynamicSharedMemorySize, 49152);

    conv_w_all<<<3072, 256>>>(Wq, Wk, Wv);
    conv_xt_all<<<dim3(32, 32, 24), dim3(32, 8)>>>(q, k, v);
    proj_mma<<<dim3(8, 8, 24), 256, 65536>>>(bq, bk, bv);
    scores_mma<<<dim3(8, 8, NBH), 256, 32768>>>();
    merge_stats<<<dim3(4, NBH), 256>>>();
    vscale_kernel<<<16384, 256>>>();
    out_mma<<<dim3(8, NBH), 256, 49152>>>(out);
}